// round 3
// baseline (speedup 1.0000x reference)
#include <cuda_runtime.h>
#include <math.h>

#define T_STEPS 256
#define B_N 64
#define D_N 1024
#define N3 (3*D_N)
#define M_TOT (T_STEPS*B_N)   // 16384

#define SCTA 128              // scan CTAs (<=148, all co-resident)
#define CPB 8                 // D columns per CTA
#define KT 64                 // h k-tile size

// Scratch (device globals: allocation-free rule)
__device__ float g_xproj[(size_t)N3 * M_TOT];   // [n][m], m = t*64+b  (201 MB)
__device__ float g_hT[2][D_N][B_N];             // h_eff double buffer, transposed [d][b]
__device__ unsigned int g_bar_count;

__global__ void reset_bar_kernel() { g_bar_count = 0u; }

// ---------------------------------------------------------------------------
// Kernel 1: x_projT[n][m] = sum_k ins[m][k] * W_i[k][n] + b_i[n]
// 128x128x8 tiled fp32 GEMM, double-buffered smem, 8x8 register tile.
// ---------------------------------------------------------------------------
__global__ void __launch_bounds__(256) gemm_xprojT(
    const float* __restrict__ A,      // ins  [M_TOT][D_N]
    const float* __restrict__ Bw,     // W_i  [D_N][N3]
    const float* __restrict__ bias)   // b_i  [N3]
{
    __shared__ float As[2][8][128];
    __shared__ float Bs[2][8][128];
    const int tid = threadIdx.x;
    const int bm = blockIdx.x * 128;
    const int bn = blockIdx.y * 128;
    const int tx = tid & 15;   // m micro-tile index
    const int ty = tid >> 4;   // n micro-tile index

    const int arow = tid >> 1;
    const int acol = (tid & 1) << 2;
    const int brow = tid >> 5;
    const int bcol = (tid & 31) << 2;

    const float* Ap = A + (size_t)(bm + arow) * D_N + acol;
    const float* Bp = Bw + (size_t)brow * N3 + (bn + bcol);

    float c[8][8];
    #pragma unroll
    for (int i = 0; i < 8; i++)
        #pragma unroll
        for (int j = 0; j < 8; j++) c[i][j] = 0.f;

    float4 pa = *(const float4*)Ap;
    float4 pb = *(const float4*)Bp;
    As[0][acol+0][arow] = pa.x; As[0][acol+1][arow] = pa.y;
    As[0][acol+2][arow] = pa.z; As[0][acol+3][arow] = pa.w;
    *(float4*)&Bs[0][brow][bcol] = pb;
    __syncthreads();

    const int NT = D_N / 8;   // 128 k-tiles
    #pragma unroll 1
    for (int kt = 0; kt < NT; ++kt) {
        const int buf = kt & 1;
        if (kt + 1 < NT) {
            pa = *(const float4*)(Ap + (kt + 1) * 8);
            pb = *(const float4*)(Bp + (size_t)(kt + 1) * 8 * N3);
        }
        #pragma unroll
        for (int k = 0; k < 8; k++) {
            float av[8], bv[8];
            float4 t0 = *(const float4*)&As[buf][k][tx << 2];
            float4 t1 = *(const float4*)&As[buf][k][64 + (tx << 2)];
            float4 t2 = *(const float4*)&Bs[buf][k][ty << 2];
            float4 t3 = *(const float4*)&Bs[buf][k][64 + (ty << 2)];
            av[0]=t0.x; av[1]=t0.y; av[2]=t0.z; av[3]=t0.w;
            av[4]=t1.x; av[5]=t1.y; av[6]=t1.z; av[7]=t1.w;
            bv[0]=t2.x; bv[1]=t2.y; bv[2]=t2.z; bv[3]=t2.w;
            bv[4]=t3.x; bv[5]=t3.y; bv[6]=t3.z; bv[7]=t3.w;
            #pragma unroll
            for (int i = 0; i < 8; i++)
                #pragma unroll
                for (int j = 0; j < 8; j++)
                    c[i][j] += av[i] * bv[j];
        }
        if (kt + 1 < NT) {
            const int nb = buf ^ 1;
            As[nb][acol+0][arow] = pa.x; As[nb][acol+1][arow] = pa.y;
            As[nb][acol+2][arow] = pa.z; As[nb][acol+3][arow] = pa.w;
            *(float4*)&Bs[nb][brow][bcol] = pb;
            __syncthreads();
        }
    }

    // Transposed store: x_projT[n][m], coalesced along m (tx fastest)
    #pragma unroll
    for (int j = 0; j < 8; j++) {
        int n = bn + (ty << 2) + (j & 3) + ((j >> 2) << 6);
        float bi = bias[n];
        size_t base = (size_t)n * M_TOT + bm;
        float4 v;
        v.x = c[0][j] + bi; v.y = c[1][j] + bi; v.z = c[2][j] + bi; v.w = c[3][j] + bi;
        *(float4*)&g_xproj[base + (tx << 2)] = v;
        v.x = c[4][j] + bi; v.y = c[5][j] + bi; v.z = c[6][j] + bi; v.w = c[7][j] + bi;
        *(float4*)&g_xproj[base + 64 + (tx << 2)] = v;
    }
}

// ---------------------------------------------------------------------------
// Grid-wide barrier: monotone counter (reset each launch by reset_bar_kernel).
// Safe because grid (128) <= SM count (148) and 1 CTA/SM -> all co-resident.
// ---------------------------------------------------------------------------
__device__ __forceinline__ void grid_barrier(unsigned int target) {
    __syncthreads();
    if (threadIdx.x == 0) {
        __threadfence();                 // publish our h writes (release)
        atomicAdd(&g_bar_count, 1u);
        while (atomicAdd(&g_bar_count, 0u) < target) { }
        __threadfence();                 // acquire side
    }
    __syncthreads();
}

// ---------------------------------------------------------------------------
// Kernel 2: persistent GRU scan. 128 CTAs x 256 threads, 8 D-cols per CTA.
// Weights for the CTA's 24 (gate,col) pairs live in smem for all 256 steps.
// h exchanged via g_hT (double buffered), one grid barrier per step.
// Cross-CTA h traffic uses .cg (L2) ops: per-SM L1 is not coherent and the
// double buffer reuses addresses every 2 steps.
// dones is int32 on device (harness converts bool -> int32).
// ---------------------------------------------------------------------------
__global__ void __launch_bounds__(256, 1) scan_kernel(
    const float* __restrict__ hiddens,        // [T][B][D]
    const int* __restrict__ dones,            // [T][B] (bool as int32)
    const float* __restrict__ init_carry,     // [B][D]
    const float* __restrict__ Wh,             // [D][3D]
    const float* __restrict__ bhn,            // [D]
    float* __restrict__ out)                  // final[B][D] then ys[T][B][D]
{
    extern __shared__ float smem[];
    float* sw = smem;                 // [24][1024] weights (cg = gate*8+col)
    float* sh = smem + 24 * D_N;      // [2][KT][64] h tiles, [k][b]

    const int tid = threadIdx.x;
    const int w = tid >> 5;           // warp 0..7 -> column within chunk
    const int l = tid & 31;
    const int b0 = l << 1;
    const int b1 = b0 + 1;
    const int d = blockIdx.x * CPB + w;

    // Stage weights: sw[cg][k] = Wh[k][gate*1024 + chunk_base + col]
    for (int idx = tid; idx < 24 * D_N; idx += 256) {
        int cg = idx % 24;
        int k = idx / 24;
        int gate = cg >> 3;
        int col = cg & 7;
        sw[cg * D_N + k] = Wh[(size_t)k * N3 + gate * D_N + blockIdx.x * CPB + col];
    }
    const float my_bhn = bhn[d];

    // Init h_eff(0) for this CTA's columns (reset with dones[0])
    for (int idx = tid; idx < CPB * B_N; idx += 256) {
        int b = idx & 63;
        int cc = idx >> 6;
        int dd = blockIdx.x * CPB + cc;
        float v = (dones[b] != 0) ? hiddens[(size_t)b * D_N + dd]
                                  : init_carry[(size_t)b * D_N + dd];
        __stcg(&g_hT[0][dd][b], v);
    }
    grid_barrier(SCTA);   // also serves as __syncthreads for sw

    const size_t OFS_YS = (size_t)B_N * D_N;
    const float* xr_base = g_xproj + (size_t)(0 * D_N + d) * M_TOT;
    const float* xz_base = g_xproj + (size_t)(1 * D_N + d) * M_TOT;
    const float* xn_base = g_xproj + (size_t)(2 * D_N + d) * M_TOT;

    for (int t = 0; t < T_STEPS; ++t) {
        const int cur = t & 1;
        const int nxt = cur ^ 1;
        const float* hc = &g_hT[cur][0][0];   // [d][b]

        float2 xr = *(const float2*)(xr_base + t * B_N + b0);
        float2 xz = *(const float2*)(xz_base + t * B_N + b0);
        float2 xn = *(const float2*)(xn_base + t * B_N + b0);
        float hcur0 = __ldcg(hc + d * B_N + b0);
        float hcur1 = __ldcg(hc + d * B_N + b1);

        float ar0=0.f, ar1=0.f, az0=0.f, az1=0.f, an0=0.f, an1=0.f;

        // --- prologue: stage h tile 0 (coalesced: g_hT is [d][b]) ---
        float4 pre[4];
        #pragma unroll
        for (int j = 0; j < 4; j++) {
            int idx = tid + j * 256;
            pre[j] = __ldcg((const float4*)(hc + (idx >> 4) * B_N + ((idx & 15) << 2)));
        }
        #pragma unroll
        for (int j = 0; j < 4; j++) {
            int idx = tid + j * 256;
            *(float4*)&sh[(idx >> 4) * B_N + ((idx & 15) << 2)] = pre[j];
        }
        __syncthreads();

        #pragma unroll 1
        for (int kt = 0; kt < D_N / KT; ++kt) {
            const int buf = kt & 1;
            if (kt + 1 < D_N / KT) {
                #pragma unroll
                for (int j = 0; j < 4; j++) {
                    int idx = tid + j * 256;
                    pre[j] = __ldcg((const float4*)(hc + ((kt + 1) * KT + (idx >> 4)) * B_N
                                                    + ((idx & 15) << 2)));
                }
            }
            const float* shb = sh + buf * (KT * B_N);
            const float* wr = sw + (w)      * D_N + kt * KT;
            const float* wz = sw + (8 + w)  * D_N + kt * KT;
            const float* wn = sw + (16 + w) * D_N + kt * KT;
            #pragma unroll
            for (int kk = 0; kk < KT; kk += 4) {
                float4 r4 = *(const float4*)(wr + kk);
                float4 z4 = *(const float4*)(wz + kk);
                float4 n4 = *(const float4*)(wn + kk);
                float2 h0 = *(const float2*)(shb + (kk + 0) * B_N + b0);
                float2 h1 = *(const float2*)(shb + (kk + 1) * B_N + b0);
                float2 h2 = *(const float2*)(shb + (kk + 2) * B_N + b0);
                float2 h3 = *(const float2*)(shb + (kk + 3) * B_N + b0);
                ar0 += r4.x*h0.x; ar1 += r4.x*h0.y;
                az0 += z4.x*h0.x; az1 += z4.x*h0.y;
                an0 += n4.x*h0.x; an1 += n4.x*h0.y;
                ar0 += r4.y*h1.x; ar1 += r4.y*h1.y;
                az0 += z4.y*h1.x; az1 += z4.y*h1.y;
                an0 += n4.y*h1.x; an1 += n4.y*h1.y;
                ar0 += r4.z*h2.x; ar1 += r4.z*h2.y;
                az0 += z4.z*h2.x; az1 += z4.z*h2.y;
                an0 += n4.z*h2.x; an1 += n4.z*h2.y;
                ar0 += r4.w*h3.x; ar1 += r4.w*h3.y;
                az0 += z4.w*h3.x; az1 += z4.w*h3.y;
                an0 += n4.w*h3.x; an1 += n4.w*h3.y;
            }
            if (kt + 1 < D_N / KT) {
                float* shn = sh + (buf ^ 1) * (KT * B_N);
                #pragma unroll
                for (int j = 0; j < 4; j++) {
                    int idx = tid + j * 256;
                    *(float4*)&shn[(idx >> 4) * B_N + ((idx & 15) << 2)] = pre[j];
                }
                __syncthreads();
            }
        }

        // Elementwise GRU cell (flax): r,z sigmoid; n tanh; convex update
        float r0 = 1.f / (1.f + expf(-(xr.x + ar0)));
        float r1 = 1.f / (1.f + expf(-(xr.y + ar1)));
        float z0 = 1.f / (1.f + expf(-(xz.x + az0)));
        float z1 = 1.f / (1.f + expf(-(xz.y + az1)));
        float n0 = tanhf(xn.x + r0 * (an0 + my_bhn));
        float n1 = tanhf(xn.y + r1 * (an1 + my_bhn));
        float h_new0 = (1.f - z0) * n0 + z0 * hcur0;
        float h_new1 = (1.f - z1) * n1 + z1 * hcur1;

        // ys[t][b][d]
        size_t yo = OFS_YS + ((size_t)t * B_N + b0) * D_N + d;
        out[yo] = h_new0;
        out[yo + D_N] = h_new1;

        if (t == T_STEPS - 1) {
            out[(size_t)b0 * D_N + d] = h_new0;   // final_carry
            out[(size_t)b1 * D_N + d] = h_new1;
        } else {
            // Publish h_eff(t+1) with the done-reset pre-applied
            int dn0 = dones[(t + 1) * B_N + b0];
            int dn1 = dones[(t + 1) * B_N + b1];
            float v0 = (dn0 != 0) ? hiddens[((size_t)(t + 1) * B_N + b0) * D_N + d] : h_new0;
            float v1 = (dn1 != 0) ? hiddens[((size_t)(t + 1) * B_N + b1) * D_N + d] : h_new1;
            __stcg(&g_hT[nxt][d][b0], v0);
            __stcg(&g_hT[nxt][d][b1], v1);
            grid_barrier((unsigned)(t + 2) * SCTA);
        }
    }
}

// ---------------------------------------------------------------------------
extern "C" void kernel_launch(void* const* d_in, const int* in_sizes, int n_in,
                              void* d_out, int out_size) {
    const float* ins        = (const float*)d_in[0];
    const float* hiddens    = (const float*)d_in[1];
    const int*   dones      = (const int*)d_in[2];      // bool -> int32 on device
    const float* init_carry = (const float*)d_in[3];
    const float* W_i        = (const float*)d_in[4];
    const float* W_h        = (const float*)d_in[5];
    const float* b_i        = (const float*)d_in[6];
    const float* b_hn       = (const float*)d_in[7];
    float*       out        = (float*)d_out;

    const int SMEM_SCAN = (24 * D_N + 2 * KT * B_N) * sizeof(float);  // 131072
    cudaFuncSetAttribute(scan_kernel, cudaFuncAttributeMaxDynamicSharedMemorySize,
                         SMEM_SCAN);

    reset_bar_kernel<<<1, 1>>>();

    dim3 g1(M_TOT / 128, N3 / 128);   // (128, 24)
    gemm_xprojT<<<g1, 256>>>(ins, W_i, b_i);

    scan_kernel<<<SCTA, 256, SMEM_SCAN>>>(hiddens, dones, init_carry, W_h, b_hn, out);
}

// round 6
// speedup vs baseline: 1.1594x; 1.1594x over previous
#include <cuda_runtime.h>
#include <cuda_bf16.h>
#include <cstdint>
#include <math.h>

#define T_STEPS 256
#define B_N 64
#define D_N 1024
#define N3 (3*D_N)
#define M_TOT (T_STEPS*B_N)   // 16384

#define SCTA 128
#define CPB 8
#define KT 64

// ---- scratch (device globals: allocation-free rule) ----
__device__ float g_xproj[(size_t)N3 * M_TOT];            // [n][m]
__device__ float g_hT[2][D_N][B_N];
__device__ unsigned int g_bar_count;
__device__ __nv_bfloat16 g_Ahi[(size_t)M_TOT * D_N];     // ins hi  [m][k]
__device__ __nv_bfloat16 g_Alo[(size_t)M_TOT * D_N];
__device__ __nv_bfloat16 g_WThi[(size_t)N3 * D_N];       // W_i^T hi [n][k]
__device__ __nv_bfloat16 g_WTlo[(size_t)N3 * D_N];

__global__ void reset_bar_kernel() { g_bar_count = 0u; }

// ============================ PTX helpers (baseline ISA only) ===============
__device__ __forceinline__ uint32_t smem_u32(const void* p) {
    uint32_t a;
    asm("{ .reg .u64 t; cvta.to.shared.u64 t, %1; cvt.u32.u64 %0, t; }" : "=r"(a) : "l"(p));
    return a;
}
#define LDSM4(r0,r1,r2,r3,addr) \
    asm volatile("ldmatrix.sync.aligned.m8n8.x4.shared.b16 {%0,%1,%2,%3}, [%4];" \
        : "=r"(r0), "=r"(r1), "=r"(r2), "=r"(r3) : "r"(addr))
#define MMA16816(c, a0,a1,a2,a3, b0,b1) \
    asm volatile("mma.sync.aligned.m16n8k16.row.col.f32.bf16.bf16.f32 " \
        "{%0,%1,%2,%3}, {%4,%5,%6,%7}, {%8,%9}, {%0,%1,%2,%3};" \
        : "+f"((c)[0]), "+f"((c)[1]), "+f"((c)[2]), "+f"((c)[3]) \
        : "r"(a0), "r"(a1), "r"(a2), "r"(a3), "r"(b0), "r"(b1))
#define CPA16(dst, src)  asm volatile("cp.async.cg.shared.global [%0], [%1], 16;" :: "r"(dst), "l"(src))
#define CP_COMMIT()      asm volatile("cp.async.commit_group;" ::: "memory")
#define CP_WAIT1()       asm volatile("cp.async.wait_group 1;" ::: "memory")
#define CP_WAIT0()       asm volatile("cp.async.wait_group 0;" ::: "memory")

// ============================ preprocessing ============================
__global__ void conv_A(const float* __restrict__ in) {
    int i = blockIdx.x * blockDim.x + threadIdx.x;
    if (i < M_TOT * D_N) {
        float a = in[i];
        __nv_bfloat16 h = __float2bfloat16(a);
        g_Ahi[i] = h;
        g_Alo[i] = __float2bfloat16(a - __bfloat162float(h));
    }
}

__global__ void conv_WT(const float* __restrict__ W) {
    __shared__ float t[32][33];
    int n0 = blockIdx.x * 32, k0 = blockIdx.y * 32;
    int tx = threadIdx.x, ty = threadIdx.y;
    t[ty][tx] = W[(size_t)(k0 + ty) * N3 + n0 + tx];
    __syncthreads();
    float v = t[tx][ty];                 // W[k0+tx][n0+ty]
    __nv_bfloat16 h = __float2bfloat16(v);
    size_t o = (size_t)(n0 + ty) * D_N + k0 + tx;
    g_WThi[o] = h;
    g_WTlo[o] = __float2bfloat16(v - __bfloat162float(h));
}

// ============================ mma.sync GEMM ============================
// x_projT[n][m] = sum_k ins[m][k]*W_i[k][n] + b_i[n]
// bf16 split: D ≈ Ahi·Bhi + Ahi·Blo + Alo·Bhi, fp32 HMMA accumulators.
// CTA tile 128x128, 8 warps (4M x 2N), warp tile 32x64, KC=32 double-buffered.
#define KC 32
#define NCH (D_N / KC)          // 32
#define ROWB 80                 // (KC+8) bf16 = 80 bytes: conflict-free ldmatrix
#define OFF_AHI 0
#define OFF_ALO 10240
#define OFF_BHI 20480
#define OFF_BLO 30720
#define BUFSTR  40960
#define SM_GEMM (2 * BUFSTR)    // 80KB (epilogue reuses first 64KB)

__global__ void __launch_bounds__(256) gemm_mma(const float* __restrict__ bias) {
    extern __shared__ char smem[];
    const uint32_t sb = smem_u32(smem);
    const int tid = threadIdx.x, lane = tid & 31, ww = tid >> 5;
    const int warp_m = ww & 3, warp_n = ww >> 2;
    const int bm = blockIdx.x * 128, bn = blockIdx.y * 128;

    float acc[2][8][4];
    #pragma unroll
    for (int i = 0; i < 2; i++)
        #pragma unroll
        for (int j = 0; j < 8; j++)
            #pragma unroll
            for (int q = 0; q < 4; q++) acc[i][j][q] = 0.f;

    const int row = tid >> 2;          // 0..63 (j loop adds 64)
    const int seg = tid & 3;

    // prologue: chunk 0 -> buffer 0
    #pragma unroll
    for (int j = 0; j < 2; j++) {
        int r = row + j * 64;
        uint32_t doff = (uint32_t)(r * ROWB + seg * 16);
        size_t ea = ((size_t)(bm + r) << 10) + seg * 8;
        size_t eb = ((size_t)(bn + r) << 10) + seg * 8;
        CPA16(sb + OFF_AHI + doff, g_Ahi + ea);
        CPA16(sb + OFF_ALO + doff, g_Alo + ea);
        CPA16(sb + OFF_BHI + doff, g_WThi + eb);
        CPA16(sb + OFF_BLO + doff, g_WTlo + eb);
    }
    CP_COMMIT();

    #pragma unroll 1
    for (int c = 0; c < NCH; ++c) {
        if (c + 1 < NCH) {
            uint32_t base = sb + ((c + 1) & 1) * BUFSTR;
            #pragma unroll
            for (int j = 0; j < 2; j++) {
                int r = row + j * 64;
                uint32_t doff = (uint32_t)(r * ROWB + seg * 16);
                size_t ea = ((size_t)(bm + r) << 10) + (c + 1) * KC + seg * 8;
                size_t eb = ((size_t)(bn + r) << 10) + (c + 1) * KC + seg * 8;
                CPA16(base + OFF_AHI + doff, g_Ahi + ea);
                CPA16(base + OFF_ALO + doff, g_Alo + ea);
                CPA16(base + OFF_BHI + doff, g_WThi + eb);
                CPA16(base + OFF_BLO + doff, g_WTlo + eb);
            }
            CP_COMMIT();
            CP_WAIT1();
        } else {
            CP_WAIT0();
        }
        __syncthreads();

        const uint32_t sbuf = sb + (c & 1) * BUFSTR;
        #pragma unroll
        for (int ks = 0; ks < 2; ++ks) {
            const uint32_t k0b = ks * 32;   // 16 bf16 = 32 bytes
            uint32_t ahi[2][4], alo[2][4];
            #pragma unroll
            for (int mt = 0; mt < 2; ++mt) {
                uint32_t ad = sbuf + OFF_AHI
                    + (uint32_t)((warp_m * 32 + mt * 16 + (lane & 15)) * ROWB)
                    + k0b + ((lane >> 4) << 4);
                LDSM4(ahi[mt][0], ahi[mt][1], ahi[mt][2], ahi[mt][3], ad);
                LDSM4(alo[mt][0], alo[mt][1], alo[mt][2], alo[mt][3], ad + (OFF_ALO - OFF_AHI));
            }
            uint32_t bhi[8][2], blo[8][2];
            #pragma unroll
            for (int p = 0; p < 4; ++p) {
                uint32_t rowB = (uint32_t)(warp_n * 64 + p * 16 + ((lane >> 4) << 3) + (lane & 7));
                uint32_t cb = k0b + (((lane >> 3) & 1) << 4);
                uint32_t bd = sbuf + OFF_BHI + rowB * ROWB + cb;
                LDSM4(bhi[2*p][0], bhi[2*p][1], bhi[2*p+1][0], bhi[2*p+1][1], bd);
                LDSM4(blo[2*p][0], blo[2*p][1], blo[2*p+1][0], blo[2*p+1][1],
                      bd + (OFF_BLO - OFF_BHI));
            }
            #pragma unroll
            for (int mt = 0; mt < 2; ++mt)
                #pragma unroll
                for (int nt = 0; nt < 8; ++nt) {
                    MMA16816(acc[mt][nt], ahi[mt][0], ahi[mt][1], ahi[mt][2], ahi[mt][3],
                             bhi[nt][0], bhi[nt][1]);
                    MMA16816(acc[mt][nt], ahi[mt][0], ahi[mt][1], ahi[mt][2], ahi[mt][3],
                             blo[nt][0], blo[nt][1]);
                    MMA16816(acc[mt][nt], alo[mt][0], alo[mt][1], alo[mt][2], alo[mt][3],
                             bhi[nt][0], bhi[nt][1]);
                }
        }
        __syncthreads();
    }

    // epilogue: stage [n_local][m_local] fp32 tile in smem, coalesced global store
    float* sc = (float*)smem;
    #pragma unroll
    for (int mt = 0; mt < 2; ++mt)
        #pragma unroll
        for (int nt = 0; nt < 8; ++nt) {
            int n_l = warp_n * 64 + nt * 8 + (lane & 3) * 2;
            int m_l = warp_m * 32 + mt * 16 + (lane >> 2);
            sc[n_l * 128 + m_l]           = acc[mt][nt][0];
            sc[(n_l + 1) * 128 + m_l]     = acc[mt][nt][1];
            sc[n_l * 128 + m_l + 8]       = acc[mt][nt][2];
            sc[(n_l + 1) * 128 + m_l + 8] = acc[mt][nt][3];
        }
    __syncthreads();
    #pragma unroll
    for (int it = 0; it < 16; ++it) {
        int idx = tid + it * 256;
        int n_l = idx >> 5, m4 = (idx & 31) << 2;
        float4 v = *(float4*)&sc[n_l * 128 + m4];
        float bi = bias[bn + n_l];
        v.x += bi; v.y += bi; v.z += bi; v.w += bi;
        *(float4*)&g_xproj[(size_t)(bn + n_l) * M_TOT + bm + m4] = v;
    }
}

// ---------------------------------------------------------------------------
// Grid-wide barrier (monotone counter; 128 CTAs all co-resident)
// ---------------------------------------------------------------------------
__device__ __forceinline__ void grid_barrier(unsigned int target) {
    __syncthreads();
    if (threadIdx.x == 0) {
        __threadfence();
        atomicAdd(&g_bar_count, 1u);
        while (atomicAdd(&g_bar_count, 0u) < target) { }
        __threadfence();
    }
    __syncthreads();
}

// ---------------------------------------------------------------------------
// Persistent GRU scan (unchanged from passing R3). dones is int32.
// ---------------------------------------------------------------------------
__global__ void __launch_bounds__(256, 1) scan_kernel(
    const float* __restrict__ hiddens,
    const int* __restrict__ dones,
    const float* __restrict__ init_carry,
    const float* __restrict__ Wh,
    const float* __restrict__ bhn,
    float* __restrict__ out)
{
    extern __shared__ float smemf[];
    float* sw = smemf;
    float* sh = smemf + 24 * D_N;

    const int tid = threadIdx.x;
    const int w = tid >> 5;
    const int l = tid & 31;
    const int b0 = l << 1;
    const int b1 = b0 + 1;
    const int d = blockIdx.x * CPB + w;

    for (int idx = tid; idx < 24 * D_N; idx += 256) {
        int cg = idx % 24;
        int k = idx / 24;
        int gate = cg >> 3;
        int col = cg & 7;
        sw[cg * D_N + k] = Wh[(size_t)k * N3 + gate * D_N + blockIdx.x * CPB + col];
    }
    const float my_bhn = bhn[d];

    for (int idx = tid; idx < CPB * B_N; idx += 256) {
        int b = idx & 63;
        int cc = idx >> 6;
        int dd = blockIdx.x * CPB + cc;
        float v = (dones[b] != 0) ? hiddens[(size_t)b * D_N + dd]
                                  : init_carry[(size_t)b * D_N + dd];
        __stcg(&g_hT[0][dd][b], v);
    }
    grid_barrier(SCTA);

    const size_t OFS_YS = (size_t)B_N * D_N;
    const float* xr_base = g_xproj + (size_t)(0 * D_N + d) * M_TOT;
    const float* xz_base = g_xproj + (size_t)(1 * D_N + d) * M_TOT;
    const float* xn_base = g_xproj + (size_t)(2 * D_N + d) * M_TOT;

    for (int t = 0; t < T_STEPS; ++t) {
        const int cur = t & 1;
        const int nxt = cur ^ 1;
        const float* hc = &g_hT[cur][0][0];

        float2 xr = *(const float2*)(xr_base + t * B_N + b0);
        float2 xz = *(const float2*)(xz_base + t * B_N + b0);
        float2 xn = *(const float2*)(xn_base + t * B_N + b0);
        float hcur0 = __ldcg(hc + d * B_N + b0);
        float hcur1 = __ldcg(hc + d * B_N + b1);

        float ar0=0.f, ar1=0.f, az0=0.f, az1=0.f, an0=0.f, an1=0.f;

        float4 pre[4];
        #pragma unroll
        for (int j = 0; j < 4; j++) {
            int idx = tid + j * 256;
            pre[j] = __ldcg((const float4*)(hc + (idx >> 4) * B_N + ((idx & 15) << 2)));
        }
        #pragma unroll
        for (int j = 0; j < 4; j++) {
            int idx = tid + j * 256;
            *(float4*)&sh[(idx >> 4) * B_N + ((idx & 15) << 2)] = pre[j];
        }
        __syncthreads();

        #pragma unroll 1
        for (int kt = 0; kt < D_N / KT; ++kt) {
            const int buf = kt & 1;
            if (kt + 1 < D_N / KT) {
                #pragma unroll
                for (int j = 0; j < 4; j++) {
                    int idx = tid + j * 256;
                    pre[j] = __ldcg((const float4*)(hc + ((kt + 1) * KT + (idx >> 4)) * B_N
                                                    + ((idx & 15) << 2)));
                }
            }
            const float* shb = sh + buf * (KT * B_N);
            const float* wr = sw + (w)      * D_N + kt * KT;
            const float* wz = sw + (8 + w)  * D_N + kt * KT;
            const float* wn = sw + (16 + w) * D_N + kt * KT;
            #pragma unroll
            for (int kk = 0; kk < KT; kk += 4) {
                float4 r4 = *(const float4*)(wr + kk);
                float4 z4 = *(const float4*)(wz + kk);
                float4 n4 = *(const float4*)(wn + kk);
                float2 h0 = *(const float2*)(shb + (kk + 0) * B_N + b0);
                float2 h1 = *(const float2*)(shb + (kk + 1) * B_N + b0);
                float2 h2 = *(const float2*)(shb + (kk + 2) * B_N + b0);
                float2 h3 = *(const float2*)(shb + (kk + 3) * B_N + b0);
                ar0 += r4.x*h0.x; ar1 += r4.x*h0.y;
                az0 += z4.x*h0.x; az1 += z4.x*h0.y;
                an0 += n4.x*h0.x; an1 += n4.x*h0.y;
                ar0 += r4.y*h1.x; ar1 += r4.y*h1.y;
                az0 += z4.y*h1.x; az1 += z4.y*h1.y;
                an0 += n4.y*h1.x; an1 += n4.y*h1.y;
                ar0 += r4.z*h2.x; ar1 += r4.z*h2.y;
                az0 += z4.z*h2.x; az1 += z4.z*h2.y;
                an0 += n4.z*h2.x; an1 += n4.z*h2.y;
                ar0 += r4.w*h3.x; ar1 += r4.w*h3.y;
                az0 += z4.w*h3.x; az1 += z4.w*h3.y;
                an0 += n4.w*h3.x; an1 += n4.w*h3.y;
            }
            if (kt + 1 < D_N / KT) {
                float* shn = sh + (buf ^ 1) * (KT * B_N);
                #pragma unroll
                for (int j = 0; j < 4; j++) {
                    int idx = tid + j * 256;
                    *(float4*)&shn[(idx >> 4) * B_N + ((idx & 15) << 2)] = pre[j];
                }
                __syncthreads();
            }
        }

        float r0 = 1.f / (1.f + expf(-(xr.x + ar0)));
        float r1 = 1.f / (1.f + expf(-(xr.y + ar1)));
        float z0 = 1.f / (1.f + expf(-(xz.x + az0)));
        float z1 = 1.f / (1.f + expf(-(xz.y + az1)));
        float n0 = tanhf(xn.x + r0 * (an0 + my_bhn));
        float n1 = tanhf(xn.y + r1 * (an1 + my_bhn));
        float h_new0 = (1.f - z0) * n0 + z0 * hcur0;
        float h_new1 = (1.f - z1) * n1 + z1 * hcur1;

        size_t yo = OFS_YS + ((size_t)t * B_N + b0) * D_N + d;
        out[yo] = h_new0;
        out[yo + D_N] = h_new1;

        if (t == T_STEPS - 1) {
            out[(size_t)b0 * D_N + d] = h_new0;
            out[(size_t)b1 * D_N + d] = h_new1;
        } else {
            int dn0 = dones[(t + 1) * B_N + b0];
            int dn1 = dones[(t + 1) * B_N + b1];
            float v0 = (dn0 != 0) ? hiddens[((size_t)(t + 1) * B_N + b0) * D_N + d] : h_new0;
            float v1 = (dn1 != 0) ? hiddens[((size_t)(t + 1) * B_N + b1) * D_N + d] : h_new1;
            __stcg(&g_hT[nxt][d][b0], v0);
            __stcg(&g_hT[nxt][d][b1], v1);
            grid_barrier((unsigned)(t + 2) * SCTA);
        }
    }
}

// ---------------------------------------------------------------------------
extern "C" void kernel_launch(void* const* d_in, const int* in_sizes, int n_in,
                              void* d_out, int out_size) {
    const float* ins        = (const float*)d_in[0];
    const float* hiddens    = (const float*)d_in[1];
    const int*   dones      = (const int*)d_in[2];
    const float* init_carry = (const float*)d_in[3];
    const float* W_i        = (const float*)d_in[4];
    const float* W_h        = (const float*)d_in[5];
    const float* b_i        = (const float*)d_in[6];
    const float* b_hn       = (const float*)d_in[7];
    float*       out        = (float*)d_out;

    const int SMEM_SCAN = (24 * D_N + 2 * KT * B_N) * sizeof(float);  // 131072
    cudaFuncSetAttribute(scan_kernel, cudaFuncAttributeMaxDynamicSharedMemorySize,
                         SMEM_SCAN);
    cudaFuncSetAttribute(gemm_mma, cudaFuncAttributeMaxDynamicSharedMemorySize,
                         SM_GEMM);

    reset_bar_kernel<<<1, 1>>>();

    conv_A<<<(M_TOT * D_N + 255) / 256, 256>>>(ins);
    conv_WT<<<dim3(N3 / 32, D_N / 32), dim3(32, 32)>>>(W_i);

    dim3 gg(M_TOT / 128, N3 / 128);   // (128, 24)
    gemm_mma<<<gg, 256, SM_GEMM>>>(b_i);

    scan_kernel<<<SCTA, 256, SMEM_SCAN>>>(hiddens, dones, init_carry, W_h, b_hn, out);
}

// round 17
// speedup vs baseline: 1.8840x; 1.6249x over previous
#include <cuda_runtime.h>
#include <cuda_bf16.h>
#include <cstdint>
#include <math.h>

#define T_STEPS 256
#define B_N 64
#define D_N 1024
#define N3 (3*D_N)
#define M_TOT (T_STEPS*B_N)   // 16384
#define SCTA 128

// ---- scratch (device globals: allocation-free rule) ----
__device__ float g_xproj[(size_t)M_TOT * N3];            // [m][n] row-major
__device__ unsigned int g_bar_count;
__device__ __nv_bfloat16 g_Ahi[(size_t)M_TOT * D_N];     // ins hi  [m][k]
__device__ __nv_bfloat16 g_Alo[(size_t)M_TOT * D_N];
__device__ __nv_bfloat16 g_WIThi[(size_t)N3 * D_N];      // W_i^T hi [n][k]
__device__ __nv_bfloat16 g_WITlo[(size_t)N3 * D_N];
__device__ __nv_bfloat16 g_WhThi[(size_t)N3 * D_N];      // W_h^T hi [n][k]
__device__ __nv_bfloat16 g_WhTlo[(size_t)N3 * D_N];
// h double buffer, plain layout: [buf][hl][b][k] bf16 (hl: 0=hi 1=lo)
__device__ __align__(16) __nv_bfloat16 g_h[2][2][B_N][D_N];
// gate partials: [ng(16)][rks(8)][ks(8)][m(64)][24] fp32  (6 MB, L2-resident)
__device__ __align__(16) float g_part[16 * 8 * 8 * 64 * 24];

__global__ void reset_bar_kernel() { g_bar_count = 0u; }

// ============================ PTX helpers (baseline ISA only) ===============
__device__ __forceinline__ uint32_t smem_u32(const void* p) {
    uint32_t a;
    asm("{ .reg .u64 t; cvta.to.shared.u64 t, %1; cvt.u32.u64 %0, t; }" : "=r"(a) : "l"(p));
    return a;
}
#define LDSM4(r0,r1,r2,r3,addr) \
    asm volatile("ldmatrix.sync.aligned.m8n8.x4.shared.b16 {%0,%1,%2,%3}, [%4];" \
        : "=r"(r0), "=r"(r1), "=r"(r2), "=r"(r3) : "r"(addr))
#define LDSM2(r0,r1,addr) \
    asm volatile("ldmatrix.sync.aligned.m8n8.x2.shared.b16 {%0,%1}, [%2];" \
        : "=r"(r0), "=r"(r1) : "r"(addr))
#define MMA16816(c, a0,a1,a2,a3, b0,b1) \
    asm volatile("mma.sync.aligned.m16n8k16.row.col.f32.bf16.bf16.f32 " \
        "{%0,%1,%2,%3}, {%4,%5,%6,%7}, {%8,%9}, {%0,%1,%2,%3};" \
        : "+f"((c)[0]), "+f"((c)[1]), "+f"((c)[2]), "+f"((c)[3]) \
        : "r"(a0), "r"(a1), "r"(a2), "r"(a3), "r"(b0), "r"(b1))
#define CPA16(dst, src)  asm volatile("cp.async.cg.shared.global [%0], [%1], 16;" :: "r"(dst), "l"(src))
#define CP_COMMIT()      asm volatile("cp.async.commit_group;" ::: "memory")
#define CP_WAIT1()       asm volatile("cp.async.wait_group 1;" ::: "memory")
#define CP_WAIT0()       asm volatile("cp.async.wait_group 0;" ::: "memory")

// ============================ preprocessing ============================
__global__ void conv_A(const float* __restrict__ in) {
    int i = blockIdx.x * blockDim.x + threadIdx.x;
    if (i < M_TOT * D_N) {
        float a = in[i];
        __nv_bfloat16 h = __float2bfloat16(a);
        g_Ahi[i] = h;
        g_Alo[i] = __float2bfloat16(a - __bfloat162float(h));
    }
}

// transpose [D_N][N3] -> [N3][D_N], bf16 hi/lo split.
// Destination globals resolved IN DEVICE CODE (host-side references to
// __device__ symbols are the host shadow — the R11/R14 zero-weights bug).
__global__ void conv_T(const float* __restrict__ W, int which) {
    __nv_bfloat16* __restrict__ hi = which ? g_WhThi : g_WIThi;
    __nv_bfloat16* __restrict__ lo = which ? g_WhTlo : g_WITlo;
    __shared__ float t[32][33];
    int n0 = blockIdx.x * 32, k0 = blockIdx.y * 32;
    int tx = threadIdx.x, ty = threadIdx.y;
    t[ty][tx] = W[(size_t)(k0 + ty) * N3 + n0 + tx];
    __syncthreads();
    float v = t[tx][ty];                 // W[k0+tx][n0+ty]
    __nv_bfloat16 h = __float2bfloat16(v);
    size_t o = (size_t)(n0 + ty) * D_N + k0 + tx;
    hi[o] = h;
    lo[o] = __float2bfloat16(v - __bfloat162float(h));
}

// ============================ mma.sync GEMM (x_proj) — proven ============
#define KC 32
#define NCH (D_N / KC)
#define ROWB 80
#define OFF_AHI 0
#define OFF_ALO 10240
#define OFF_BHI 20480
#define OFF_BLO 30720
#define BUFSTR  40960
#define SM_GEMM (2 * BUFSTR)

__global__ void __launch_bounds__(256) gemm_mma(const float* __restrict__ bias) {
    extern __shared__ char smem[];
    const uint32_t sb = smem_u32(smem);
    const int tid = threadIdx.x, lane = tid & 31, ww = tid >> 5;
    const int warp_m = ww & 3, warp_n = ww >> 2;
    const int bm = blockIdx.x * 128, bn = blockIdx.y * 128;

    float acc[2][8][4];
    #pragma unroll
    for (int i = 0; i < 2; i++)
        #pragma unroll
        for (int j = 0; j < 8; j++)
            #pragma unroll
            for (int q = 0; q < 4; q++) acc[i][j][q] = 0.f;

    const int row = tid >> 2;
    const int seg = tid & 3;

    #pragma unroll
    for (int j = 0; j < 2; j++) {
        int r = row + j * 64;
        uint32_t doff = (uint32_t)(r * ROWB + seg * 16);
        size_t ea = ((size_t)(bm + r) << 10) + seg * 8;
        size_t eb = ((size_t)(bn + r) << 10) + seg * 8;
        CPA16(sb + OFF_AHI + doff, g_Ahi + ea);
        CPA16(sb + OFF_ALO + doff, g_Alo + ea);
        CPA16(sb + OFF_BHI + doff, g_WIThi + eb);
        CPA16(sb + OFF_BLO + doff, g_WITlo + eb);
    }
    CP_COMMIT();

    #pragma unroll 1
    for (int c = 0; c < NCH; ++c) {
        if (c + 1 < NCH) {
            uint32_t base = sb + ((c + 1) & 1) * BUFSTR;
            #pragma unroll
            for (int j = 0; j < 2; j++) {
                int r = row + j * 64;
                uint32_t doff = (uint32_t)(r * ROWB + seg * 16);
                size_t ea = ((size_t)(bm + r) << 10) + (c + 1) * KC + seg * 8;
                size_t eb = ((size_t)(bn + r) << 10) + (c + 1) * KC + seg * 8;
                CPA16(base + OFF_AHI + doff, g_Ahi + ea);
                CPA16(base + OFF_ALO + doff, g_Alo + ea);
                CPA16(base + OFF_BHI + doff, g_WIThi + eb);
                CPA16(base + OFF_BLO + doff, g_WITlo + eb);
            }
            CP_COMMIT();
            CP_WAIT1();
        } else {
            CP_WAIT0();
        }
        __syncthreads();

        const uint32_t sbuf = sb + (c & 1) * BUFSTR;
        #pragma unroll
        for (int ks = 0; ks < 2; ++ks) {
            const uint32_t k0b = ks * 32;
            uint32_t ahi[2][4], alo[2][4];
            #pragma unroll
            for (int mt = 0; mt < 2; ++mt) {
                uint32_t ad = sbuf + OFF_AHI
                    + (uint32_t)((warp_m * 32 + mt * 16 + (lane & 15)) * ROWB)
                    + k0b + ((lane >> 4) << 4);
                LDSM4(ahi[mt][0], ahi[mt][1], ahi[mt][2], ahi[mt][3], ad);
                LDSM4(alo[mt][0], alo[mt][1], alo[mt][2], alo[mt][3], ad + (OFF_ALO - OFF_AHI));
            }
            uint32_t bhi[8][2], blo[8][2];
            #pragma unroll
            for (int p = 0; p < 4; ++p) {
                uint32_t rowB = (uint32_t)(warp_n * 64 + p * 16 + ((lane >> 4) << 3) + (lane & 7));
                uint32_t cb = k0b + (((lane >> 3) & 1) << 4);
                uint32_t bd = sbuf + OFF_BHI + rowB * ROWB + cb;
                LDSM4(bhi[2*p][0], bhi[2*p][1], bhi[2*p+1][0], bhi[2*p+1][1], bd);
                LDSM4(blo[2*p][0], blo[2*p][1], blo[2*p+1][0], blo[2*p+1][1],
                      bd + (OFF_BLO - OFF_BHI));
            }
            #pragma unroll
            for (int mt = 0; mt < 2; ++mt)
                #pragma unroll
                for (int nt = 0; nt < 8; ++nt) {
                    MMA16816(acc[mt][nt], ahi[mt][0], ahi[mt][1], ahi[mt][2], ahi[mt][3],
                             bhi[nt][0], bhi[nt][1]);
                    MMA16816(acc[mt][nt], ahi[mt][0], ahi[mt][1], ahi[mt][2], ahi[mt][3],
                             blo[nt][0], blo[nt][1]);
                    MMA16816(acc[mt][nt], alo[mt][0], alo[mt][1], alo[mt][2], alo[mt][3],
                             bhi[nt][0], bhi[nt][1]);
                }
        }
        __syncthreads();
    }

    // direct fragment store to g_xproj[m][n], +bias (mapping proven in R6)
    #pragma unroll
    for (int mt = 0; mt < 2; ++mt)
        #pragma unroll
        for (int nt = 0; nt < 8; ++nt) {
            int m = bm + warp_m * 32 + mt * 16 + (lane >> 2);
            int n = bn + warp_n * 64 + nt * 8 + 2 * (lane & 3);
            float b0 = bias[n], b1 = bias[n + 1];
            float2 v0 = make_float2(acc[mt][nt][0] + b0, acc[mt][nt][1] + b1);
            float2 v1 = make_float2(acc[mt][nt][2] + b0, acc[mt][nt][3] + b1);
            *(float2*)&g_xproj[(size_t)m * N3 + n] = v0;
            *(float2*)&g_xproj[(size_t)(m + 8) * N3 + n] = v1;
        }
}

// ---------------------------------------------------------------------------
__device__ __forceinline__ void grid_barrier(unsigned int target) {
    __syncthreads();
    if (threadIdx.x == 0) {
        __threadfence();
        atomicAdd(&g_bar_count, 1u);
        while (atomicAdd(&g_bar_count, 0u) < target) { }
        __threadfence();
    }
    __syncthreads();
}

// ============================ k-split tensor-core GRU scan ==================
// 128 CTAs = 16 n-groups (192 n = 3 gates x 64 d) x 8 k-slices (128 k).
// Phase 1: mma partials for (ng, k-slice).  barrier.
// Phase 2: CTA (ng,ks) reduces 8 slices for d = ng*64+ks*8..+8, cell, publish.
#define PAD_ROW 272                       // 128 k * 2B + 16 pad (conflict-free)
#define SW_HL   (192 * PAD_ROW)           // 52224
#define SA_HL   (64 * PAD_ROW)            // 17408
#define SM_W 0
#define SM_A (2 * SW_HL)                  // 104448
#define SM_G (SM_A + 2 * SA_HL)           // 139264: float [64][24]
#define SM_H (SM_G + 6144)                // 145408: float [512]
#define SM_PUB (SM_H + 2048)              // 147456: bf16 hi[512], lo[512]
#define SM_SCAN (SM_PUB + 2048)           // 149504

__global__ void __launch_bounds__(256, 1) scan_ks(
    const float* __restrict__ hiddens,       // [T][B][D]
    const int* __restrict__ dones,           // [T][B]
    const float* __restrict__ init_carry,    // [B][D]
    const float* __restrict__ bhn,           // [D]
    float* __restrict__ out)                 // final[B][D] then ys[T][B][D]
{
    extern __shared__ char smem[];
    const uint32_t sb = smem_u32(smem);
    const int tid = threadIdx.x, lane = tid & 31, wid = tid >> 5;
    const int wm = wid & 3, wn = wid >> 2;        // m-tile, n-half
    const int ng = blockIdx.x >> 3, ks = blockIdx.x & 7;
    const int d0 = ng * 64 + ks * 8;              // owned d-slice base

    // ---- stage W_h^T slice: 192 rows x 128 k, hi/lo ----
    for (int idx = tid; idx < 6144; idx += 256) {
        int hl = idx / 3072, rem = idx % 3072;
        int nl = rem >> 4, ch = rem & 15;
        int nglob = (nl >> 6) * 1024 + ng * 64 + (nl & 63);
        const __nv_bfloat16* src = hl ? g_WhTlo : g_WhThi;
        *(uint4*)(smem + SM_W + hl * SW_HL + nl * PAD_ROW + ch * 16) =
            *(const uint4*)(src + (size_t)nglob * 1024 + ks * 128 + ch * 8);
    }

    // ---- init h_eff(0): local fp32 + publish bf16 hi/lo ----
    float* SH = (float*)(smem + SM_H);
    for (int idx = tid; idx < 512; idx += 256) {
        int b = idx >> 3, col = idx & 7, d = d0 + col;
        float v = (dones[b] != 0) ? hiddens[(size_t)b * 1024 + d]
                                  : init_carry[(size_t)b * 1024 + d];
        SH[idx] = v;
        __nv_bfloat16 hv = __float2bfloat16(v);
        *(__nv_bfloat16*)(smem + SM_PUB + idx * 2) = hv;
        *(__nv_bfloat16*)(smem + SM_PUB + 1024 + idx * 2) =
            __float2bfloat16(v - __bfloat162float(hv));
    }
    __syncthreads();
    if (tid < 128) {
        int hl = tid >> 6, b = tid & 63;
        uint4 v = *(uint4*)(smem + SM_PUB + hl * 1024 + b * 16);
        *(uint4*)&g_h[0][hl][b][d0] = v;
    }
    unsigned int nb = 1;
    grid_barrier(nb * SCTA);

    float* SG = (float*)(smem + SM_G);
    const int r_row = wm * 16 + (lane & 15);

    #pragma unroll 1
    for (int t = 0; t < T_STEPS; ++t) {
        const int cur = t & 1, nxt = cur ^ 1;

        // ---- phase 1: load h slice (hi/lo) via cp.async.cg ----
        #pragma unroll
        for (int i = 0; i < 8; ++i) {
            int o = tid + i * 256;            // 0..2047
            int hl = o >> 10, rem = o & 1023;
            int b = rem >> 4, ch = rem & 15;
            CPA16(sb + SM_A + hl * SA_HL + b * PAD_ROW + ch * 16,
                  &g_h[cur][hl][b][ks * 128 + ch * 8]);
        }
        CP_COMMIT();
        CP_WAIT0();
        __syncthreads();

        float acc[12][4];
        #pragma unroll
        for (int j = 0; j < 12; ++j)
            #pragma unroll
            for (int q = 0; q < 4; ++q) acc[j][q] = 0.f;

        #pragma unroll
        for (int kst = 0; kst < 8; ++kst) {
            uint32_t aaddr = sb + SM_A + (uint32_t)(r_row * PAD_ROW)
                             + kst * 32 + ((lane >> 4) << 4);
            uint32_t ah0, ah1, ah2, ah3, al0, al1, al2, al3;
            LDSM4(ah0, ah1, ah2, ah3, aaddr);
            LDSM4(al0, al1, al2, al3, aaddr + SA_HL);
            #pragma unroll
            for (int j = 0; j < 12; ++j) {
                uint32_t baddr = sb + SM_W
                    + (uint32_t)((wn * 96 + j * 8 + (lane & 7)) * PAD_ROW)
                    + kst * 32 + (((lane >> 3) & 1) << 4);
                uint32_t bh0, bh1, bl0, bl1;
                LDSM2(bh0, bh1, baddr);
                LDSM2(bl0, bl1, baddr + SW_HL);
                MMA16816(acc[j], ah0, ah1, ah2, ah3, bh0, bh1);
                MMA16816(acc[j], ah0, ah1, ah2, ah3, bl0, bl1);
                MMA16816(acc[j], al0, al1, al2, al3, bh0, bh1);
            }
        }

        // ---- store partials grouped by reducer ----
        #pragma unroll
        for (int j = 0; j < 12; ++j) {
            int nlb = wn * 96 + j * 8;
            int g = nlb >> 6, c = nlb & 63, rks = c >> 3;
            size_t base = ((((size_t)(ng * 8 + rks)) * 8 + ks) * 64
                           + wm * 16 + (lane >> 2)) * 24 + g * 8 + 2 * (lane & 3);
            *(float2*)&g_part[base] = make_float2(acc[j][0], acc[j][1]);
            *(float2*)&g_part[base + 8 * 24] = make_float2(acc[j][2], acc[j][3]);
        }
        ++nb;
        grid_barrier(nb * SCTA);

        // ---- phase 2: reduce 8 slices for own 24 n-cols ----
        for (int idx = tid; idx < 384; idx += 256) {
            int m = idx / 6, jg = idx % 6;    // 4 consecutive floats
            size_t base = (((size_t)(ng * 8 + ks)) * 8 * 64 + m) * 24 + jg * 4;
            float4 s = make_float4(0.f, 0.f, 0.f, 0.f);
            #pragma unroll
            for (int sl = 0; sl < 8; ++sl) {
                float4 p = __ldcg((const float4*)&g_part[base + (size_t)sl * 64 * 24]);
                s.x += p.x; s.y += p.y; s.z += p.z; s.w += p.w;
            }
            *(float4*)&SG[m * 24 + jg * 4] = s;
        }
        __syncthreads();

        // ---- cell + publish prep ----
        for (int idx = tid; idx < 512; idx += 256) {
            const int b = idx >> 3, col = idx & 7, d = d0 + col;
            const float rr = SG[b * 24 + col];
            const float zz = SG[b * 24 + 8 + col];
            const float nn = SG[b * 24 + 16 + col];
            const size_t xm = ((size_t)t * 64 + b) * N3;
            const float xr = g_xproj[xm + d];
            const float xz = g_xproj[xm + 1024 + d];
            const float xn = g_xproj[xm + 2048 + d];
            const float hc = SH[idx];
            const float r = 1.f / (1.f + expf(-(xr + rr)));
            const float z = 1.f / (1.f + expf(-(xz + zz)));
            const float n = tanhf(xn + r * (nn + bhn[d]));
            const float hnew = (1.f - z) * n + z * hc;
            out[65536 + ((size_t)t * 64 + b) * 1024 + d] = hnew;
            if (t == T_STEPS - 1) {
                out[(size_t)b * 1024 + d] = hnew;
            } else {
                float v = hnew;
                if (dones[(t + 1) * 64 + b] != 0)
                    v = hiddens[((size_t)(t + 1) * 64 + b) * 1024 + d];
                SH[idx] = v;
                __nv_bfloat16 hv = __float2bfloat16(v);
                *(__nv_bfloat16*)(smem + SM_PUB + idx * 2) = hv;
                *(__nv_bfloat16*)(smem + SM_PUB + 1024 + idx * 2) =
                    __float2bfloat16(v - __bfloat162float(hv));
            }
        }
        if (t < T_STEPS - 1) {
            __syncthreads();
            if (tid < 128) {
                int hl = tid >> 6, b = tid & 63;
                uint4 v = *(uint4*)(smem + SM_PUB + hl * 1024 + b * 16);
                *(uint4*)&g_h[nxt][hl][b][d0] = v;
            }
            ++nb;
            grid_barrier(nb * SCTA);
        }
    }
}

// ---------------------------------------------------------------------------
extern "C" void kernel_launch(void* const* d_in, const int* in_sizes, int n_in,
                              void* d_out, int out_size) {
    const float* ins        = (const float*)d_in[0];
    const float* hiddens    = (const float*)d_in[1];
    const int*   dones      = (const int*)d_in[2];
    const float* init_carry = (const float*)d_in[3];
    const float* W_i        = (const float*)d_in[4];
    const float* W_h        = (const float*)d_in[5];
    const float* b_i        = (const float*)d_in[6];
    const float* b_hn       = (const float*)d_in[7];
    float*       out        = (float*)d_out;

    cudaFuncSetAttribute(gemm_mma, cudaFuncAttributeMaxDynamicSharedMemorySize, SM_GEMM);
    cudaFuncSetAttribute(scan_ks, cudaFuncAttributeMaxDynamicSharedMemorySize, SM_SCAN);

    reset_bar_kernel<<<1, 1>>>();

    conv_A<<<(M_TOT * D_N + 255) / 256, 256>>>(ins);
    conv_T<<<dim3(N3 / 32, D_N / 32), dim3(32, 32)>>>(W_i, 0);
    conv_T<<<dim3(N3 / 32, D_N / 32), dim3(32, 32)>>>(W_h, 1);

    dim3 gg(M_TOT / 128, N3 / 128);   // (128, 24)
    gemm_mma<<<gg, 256, SM_GEMM>>>(b_i);

    scan_ks<<<SCTA, 256, SM_SCAN>>>(hiddens, dones, init_carry, b_hn, out);
}